// round 1
// baseline (speedup 1.0000x reference)
#include <cuda_runtime.h>

// ---------------------------------------------------------------------------
// PixelEachSubstitutor: per-pixel tiny transformer, heavily structure-exploited.
//   - encoder sequence rows 9..80 are identically zero -> 9x9 attention + closed
//     form correction; rows >=9 collapse to one shared vector u.
//   - decoder self-attention block is pixel-independent -> precomputed once.
//   - exp via FMA-pipe polynomial (avoids MUFU bottleneck).
// ---------------------------------------------------------------------------

__device__ float g_y1[320];   // post-SA, post-LN1 decoder state (10 x 32)
__device__ float g_qc[320];   // cross-attention queries y1 @ WqCA^T (10 x 32)
__device__ float g_S[32];     // sum_{p=9..80} ffV_w[v][p]

__device__ __forceinline__ float fast_exp(float x) {
    // exp(x) = 2^(x*log2e); rint via magic constant; degree-5 poly on [-0.5,0.5]
    float t = x * 1.4426950408889634f;
    t = fmaxf(t, -110.0f);                      // keep exponent in range
    float z = t + 12582912.0f;                  // 1.5 * 2^23
    int   n = __float_as_int(z) - 0x4B400000;   // = rint(t)
    float r = t - (z - 12582912.0f);            // in [-0.5, 0.5]
    float p = 1.3333558e-3f;
    p = fmaf(p, r, 9.6181291e-3f);
    p = fmaf(p, r, 5.5504109e-2f);
    p = fmaf(p, r, 2.4022651e-1f);
    p = fmaf(p, r, 6.9314718e-1f);
    p = fmaf(p, r, 1.0f);
    return __int_as_float((n + 127) << 23) * p;
}

// ---------------------------------------------------------------------------
// Precompute kernel: 1 block, 320 threads. Pixel-independent decoder SA block.
// ---------------------------------------------------------------------------
__global__ void __launch_bounds__(320) precompute_kernel(
    const float* __restrict__ Vf,      // (10,32)
    const float* __restrict__ sa_in,   // (96,32)
    const float* __restrict__ sa_out,  // (32,32)
    const float* __restrict__ dln1,    // (32)
    const float* __restrict__ ca_in,   // (96,32)
    const float* __restrict__ ffv)     // (32,81)
{
    __shared__ float qs[320], ks[320], vs[320], os_[320], rr[320], y1s[320];
    int t = threadIdx.x;
    int i = t >> 5, h = t & 31;

    // qkv for self-attention (nhead=32, hd=1)
    float aq = 0.f, ak = 0.f, av = 0.f;
    #pragma unroll 8
    for (int v = 0; v < 32; v++) {
        float f = Vf[i * 32 + v];
        aq = fmaf(sa_in[h * 32 + v], f, aq);
        ak = fmaf(sa_in[(32 + h) * 32 + v], f, ak);
        av = fmaf(sa_in[(64 + h) * 32 + v], f, av);
    }
    qs[t] = aq; ks[t] = ak; vs[t] = av;
    __syncthreads();

    // per-(i,h) softmax over 10 keys, hd=1 so score = q*k (scale 1)
    {
        float qv = qs[i * 32 + h];
        float m = -1e30f;
        #pragma unroll
        for (int j = 0; j < 10; j++) m = fmaxf(m, qv * ks[j * 32 + h]);
        float den = 0.f, num = 0.f;
        #pragma unroll
        for (int j = 0; j < 10; j++) {
            float e = fast_exp(fmaf(qv, ks[j * 32 + h], -m));
            den += e;
            num = fmaf(e, vs[j * 32 + h], num);
        }
        os_[t] = num / den;
    }
    __syncthreads();

    // out projection + residual
    {
        int c = h;
        float acc = 0.f;
        #pragma unroll 8
        for (int hh = 0; hh < 32; hh++)
            acc = fmaf(sa_out[c * 32 + hh], os_[i * 32 + hh], acc);
        rr[t] = Vf[i * 32 + c] + acc;
    }
    __syncthreads();

    // LayerNorm rows -> y1
    if (t < 10) {
        float mean = 0.f;
        for (int c = 0; c < 32; c++) mean += rr[t * 32 + c];
        mean *= (1.0f / 32.0f);
        float var = 0.f;
        for (int c = 0; c < 32; c++) { float d = rr[t * 32 + c] - mean; var = fmaf(d, d, var); }
        var *= (1.0f / 32.0f);
        float inv = rsqrtf(var + 1e-5f);
        for (int c = 0; c < 32; c++) {
            float yv = (rr[t * 32 + c] - mean) * inv * dln1[c];
            y1s[t * 32 + c] = yv;
            g_y1[t * 32 + c] = yv;
        }
    }
    __syncthreads();

    // cross-attention queries
    {
        float acc = 0.f;
        #pragma unroll 8
        for (int v = 0; v < 32; v++)
            acc = fmaf(ca_in[h * 32 + v], y1s[i * 32 + v], acc);
        g_qc[t] = acc;
    }
    // ffV tail sums
    if (t < 32) {
        float s = 0.f;
        for (int p = 9; p < 81; p++) s += ffv[t * 81 + p];
        g_S[t] = s;
    }
}

// ---------------------------------------------------------------------------
// Main kernel: one block (128 threads) per pixel, 14400 blocks.
// ---------------------------------------------------------------------------
__global__ void __launch_bounds__(128) main_kernel(
    const float* __restrict__ x,
    const float* __restrict__ enc_in, const float* __restrict__ enc_out,
    const float* __restrict__ el1, const float* __restrict__ el2,
    const float* __restrict__ eln1, const float* __restrict__ eln2,
    const float* __restrict__ ffv,
    const float* __restrict__ ca_in, const float* __restrict__ ca_out,
    const float* __restrict__ dl1, const float* __restrict__ dl2,
    const float* __restrict__ dln2, const float* __restrict__ dln3,
    const float* __restrict__ wd0, const float* __restrict__ wd1,
    float* __restrict__ out)
{
    // ---- weights (staged, bank-conflict-aware padded layouts) ----
    __shared__ float sWin[363];          // enc in_proj (33x11)
    __shared__ float sWout[121];         // enc out_proj (11x11)
    __shared__ float sLin1[11], sLin2[11], sLn1[11], sLn2[11];
    __shared__ float sFfvT[9 * 32];      // [p*32+v]
    __shared__ float sS[32];
    __shared__ float sQc[320];           // [i*32+h]
    __shared__ float sY1[320];
    __shared__ float sWk[32 * 33];       // [h*33+v]
    __shared__ float sWv[32 * 33];
    __shared__ float sWo2[32 * 33];      // [c*33+h]
    __shared__ float sDlin1[32], sDlin2[32], sDln2w[32], sDln3w[32];
    __shared__ float sWd0[8 * 33];       // [k*33+c]
    __shared__ float sWd1[8];
    // ---- activations ----
    __shared__ float f9s[9 * 12];        // [p*12+c]
    __shared__ float qes[9 * 12], kes[9 * 12], ves[9 * 12];
    __shared__ float scs[9 * 12];        // scores -> exp weights
    __shared__ float ous[12];            // uniform-row attention output (pre-proj)
    __shared__ float invd[9];
    __shared__ float ggs[10 * 12];       // rows 0..8 real, row 9 uniform
    __shared__ float f2s[10 * 12];
    __shared__ __align__(16) float mems[11 * 36];  // [c*36+v], float4-aligned rows
    __shared__ float kcs[11 * 33], vcs[11 * 33];   // [j*33+h]
    __shared__ float oas[320];           // [i*32+h]
    __shared__ float y2s[10 * 33];
    __shared__ float y3s[10 * 33];
    __shared__ float hks[80];

    const int tid = threadIdx.x;
    const int b = blockIdx.x;
    const int n = b / 900;
    const int rem = b % 900;
    const int pi = rem / 30;
    const int pj = rem % 30;

    // ---- stage weights ----
    for (int t = tid; t < 363; t += 128) sWin[t] = enc_in[t];
    for (int t = tid; t < 121; t += 128) sWout[t] = enc_out[t];
    if (tid < 11) {
        sLin1[tid] = el1[tid]; sLin2[tid] = el2[tid];
        sLn1[tid] = eln1[tid]; sLn2[tid] = eln2[tid];
    }
    for (int t = tid; t < 288; t += 128) {
        int v = t / 9, p = t % 9;
        sFfvT[p * 32 + v] = ffv[v * 81 + p];
    }
    if (tid < 32) {
        sS[tid] = g_S[tid];
        sDlin1[tid] = dl1[tid]; sDlin2[tid] = dl2[tid];
        sDln2w[tid] = dln2[tid]; sDln3w[tid] = dln3[tid];
    }
    for (int t = tid; t < 320; t += 128) { sQc[t] = g_qc[t]; sY1[t] = g_y1[t]; }
    for (int t = tid; t < 1024; t += 128) {
        int hh = t >> 5, v = t & 31;
        sWk[hh * 33 + v] = ca_in[(32 + hh) * 32 + v];
        sWv[hh * 33 + v] = ca_in[(64 + hh) * 32 + v];
        sWo2[hh * 33 + v] = ca_out[t];   // natural (c,h) padded
    }
    for (int t = tid; t < 256; t += 128) {
        int k = t >> 5, c = t & 31;
        sWd0[k * 33 + c] = wd0[t];
    }
    if (tid < 8) sWd1[tid] = wd1[tid];

    // ---- build f9 (9 real sequence rows; rows 9..80 are zero by construction) ----
    for (int t = tid; t < 99; t += 128) {
        int p = t / 11, c = t % 11;
        float val;
        if (c == 10) {
            val = 1.0f;  // ones channel (unpadded in reference -> 1 everywhere)
        } else {
            int ii = pi + p / 3 - 1, jj = pj + p % 3 - 1;
            val = (ii >= 0 && ii < 30 && jj >= 0 && jj < 30)
                      ? x[((n * 10 + c) * 30 + ii) * 30 + jj] : 0.0f;
        }
        f9s[p * 12 + c] = val;
    }
    __syncthreads();

    // ---- encoder qkv (rows 0..8 only) ----
    for (int idx = tid; idx < 297; idx += 128) {
        int which = idx / 99, r = idx % 99;
        int p = r / 11, a = r % 11;
        const float* W = &sWin[(which * 11 + a) * 11];
        const float* f = &f9s[p * 12];
        float acc = 0.f;
        #pragma unroll
        for (int c = 0; c < 11; c++) acc = fmaf(W[c], f[c], acc);
        float* dst = (which == 0) ? qes : (which == 1) ? kes : ves;
        dst[p * 12 + a] = acc;
    }
    __syncthreads();

    // ---- 9x9 scores (+ uniform-row value mean in parallel) ----
    for (int idx = tid; idx < 81; idx += 128) {
        int i = idx / 9, j = idx % 9;
        float acc = 0.f;
        #pragma unroll
        for (int a = 0; a < 11; a++) acc = fmaf(qes[i * 12 + a], kes[j * 12 + a], acc);
        scs[i * 12 + j] = acc * 0.30151134457776363f;  // 1/sqrt(11)
    }
    if (tid >= 96 && tid < 107) {
        int a = tid - 96;
        float s = 0.f;
        #pragma unroll
        for (int j = 0; j < 9; j++) s += ves[j * 12 + a];
        ous[a] = s * (1.0f / 81.0f);   // softmax over all-zero scores = uniform(81)
    }
    __syncthreads();

    // ---- row softmax with +72 zero-key correction ----
    if (tid < 9) {
        int i = tid;
        float m = 0.0f;  // zero-scores participate in the max
        #pragma unroll
        for (int j = 0; j < 9; j++) m = fmaxf(m, scs[i * 12 + j]);
        float sum = 72.0f * fast_exp(-m);   // 72 padded keys, score 0
        #pragma unroll
        for (int j = 0; j < 9; j++) {
            float e = fast_exp(scs[i * 12 + j] - m);
            scs[i * 12 + j] = e;
            sum += e;
        }
        invd[i] = 1.0f / sum;
    }
    __syncthreads();

    // ---- attn @ v (result into qes, dead by now) ----
    for (int idx = tid; idx < 99; idx += 128) {
        int i = idx / 11, a = idx % 11;
        float acc = 0.f;
        #pragma unroll
        for (int j = 0; j < 9; j++) acc = fmaf(scs[i * 12 + j], ves[j * 12 + a], acc);
        qes[i * 12 + a] = acc * invd[i];
    }
    __syncthreads();

    // ---- out_proj + residual -> gg (row 9 = shared uniform row, residual 0) ----
    for (int idx = tid; idx < 110; idx += 128) {
        int i = idx / 11, c = idx % 11;
        const float* osrc = (i < 9) ? &qes[i * 12] : ous;
        float acc = (i < 9) ? f9s[i * 12 + c] : 0.0f;
        #pragma unroll
        for (int a = 0; a < 11; a++) acc = fmaf(sWout[c * 11 + a], osrc[a], acc);
        ggs[i * 12 + c] = acc;
    }
    __syncthreads();

    // ---- LN1 + FFN + LN2 per row (10 distinct rows) ----
    if (tid < 10) {
        int rw = tid;
        float l[11];
        float mean = 0.f;
        #pragma unroll
        for (int c = 0; c < 11; c++) { l[c] = ggs[rw * 12 + c]; mean += l[c]; }
        mean *= (1.0f / 11.0f);
        float var = 0.f;
        #pragma unroll
        for (int c = 0; c < 11; c++) { float d = l[c] - mean; var = fmaf(d, d, var); }
        var *= (1.0f / 11.0f);
        float inv = rsqrtf(var + 1e-5f);
        float s1 = 0.f;
        #pragma unroll
        for (int c = 0; c < 11; c++) {
            l[c] = (l[c] - mean) * inv * sLn1[c];
            s1 = fmaf(l[c], sLin1[c], s1);
        }
        s1 = fmaxf(s1, 0.0f);
        float mean2 = 0.f;
        #pragma unroll
        for (int c = 0; c < 11; c++) { l[c] = fmaf(s1, sLin2[c], l[c]); mean2 += l[c]; }
        mean2 *= (1.0f / 11.0f);
        float var2 = 0.f;
        #pragma unroll
        for (int c = 0; c < 11; c++) { float d = l[c] - mean2; var2 = fmaf(d, d, var2); }
        var2 *= (1.0f / 11.0f);
        float inv2 = rsqrtf(var2 + 1e-5f);
        #pragma unroll
        for (int c = 0; c < 11; c++)
            f2s[rw * 12 + c] = (l[c] - mean2) * inv2 * sLn2[c];
    }
    __syncthreads();

    // ---- mem = f2[0..8] @ ffv9^T + rank-1 tail u * S ----
    for (int idx = tid; idx < 352; idx += 128) {
        int c = idx >> 5, v = idx & 31;
        float acc = f2s[9 * 12 + c] * sS[v];
        #pragma unroll
        for (int p = 0; p < 9; p++) acc = fmaf(f2s[p * 12 + c], sFfvT[p * 32 + v], acc);
        mems[c * 36 + v] = acc;
    }
    __syncthreads();

    // ---- kc/vc: register-cached weight rows, float4 broadcast mem rows ----
    if (tid < 64) {
        int h = tid & 31, which = tid >> 5;
        const float* W = which ? &sWv[h * 33] : &sWk[h * 33];
        float w[32];
        #pragma unroll
        for (int v = 0; v < 32; v++) w[v] = W[v];
        float* dst = which ? vcs : kcs;
        #pragma unroll
        for (int j = 0; j < 11; j++) {
            const float4* mr = (const float4*)&mems[j * 36];
            float acc = 0.f;
            #pragma unroll
            for (int q4 = 0; q4 < 8; q4++) {
                float4 m4 = mr[q4];
                acc = fmaf(w[4 * q4 + 0], m4.x, acc);
                acc = fmaf(w[4 * q4 + 1], m4.y, acc);
                acc = fmaf(w[4 * q4 + 2], m4.z, acc);
                acc = fmaf(w[4 * q4 + 3], m4.w, acc);
            }
            dst[j * 33 + h] = acc;
        }
    }
    __syncthreads();

    // ---- cross-attention (hd=1): per (i,h) softmax over 11 keys ----
    for (int idx = tid; idx < 320; idx += 128) {
        int h = idx & 31, i = idx >> 5;
        float qch = sQc[i * 32 + h];
        float m = -1e30f;
        #pragma unroll
        for (int j = 0; j < 11; j++) m = fmaxf(m, qch * kcs[j * 33 + h]);
        float den = 0.f, num = 0.f;
        #pragma unroll
        for (int j = 0; j < 11; j++) {
            float e = fast_exp(fmaf(qch, kcs[j * 33 + h], -m));
            den += e;
            num = fmaf(e, vcs[j * 33 + h], num);
        }
        oas[i * 32 + h] = num / den;
    }
    __syncthreads();

    // ---- CA out projection + residual ----
    for (int idx = tid; idx < 320; idx += 128) {
        int c = idx & 31, i = idx >> 5;
        float acc = 0.f;
        #pragma unroll
        for (int hh = 0; hh < 32; hh++)
            acc = fmaf(sWo2[c * 33 + hh], oas[i * 32 + hh], acc);
        y2s[i * 33 + c] = sY1[i * 32 + c] + acc;
    }
    __syncthreads();

    // ---- LN2 + FFN + LN3 per row ----
    if (tid < 10) {
        int rw = tid;
        float l[32];
        float mean = 0.f;
        #pragma unroll
        for (int c = 0; c < 32; c++) { l[c] = y2s[rw * 33 + c]; mean += l[c]; }
        mean *= (1.0f / 32.0f);
        float var = 0.f;
        #pragma unroll
        for (int c = 0; c < 32; c++) { float d = l[c] - mean; var = fmaf(d, d, var); }
        var *= (1.0f / 32.0f);
        float inv = rsqrtf(var + 1e-5f);
        float s1 = 0.f;
        #pragma unroll
        for (int c = 0; c < 32; c++) {
            l[c] = (l[c] - mean) * inv * sDln2w[c];
            s1 = fmaf(l[c], sDlin1[c], s1);
        }
        s1 = fmaxf(s1, 0.0f);
        float mean2 = 0.f;
        #pragma unroll
        for (int c = 0; c < 32; c++) { l[c] = fmaf(s1, sDlin2[c], l[c]); mean2 += l[c]; }
        mean2 *= (1.0f / 32.0f);
        float var2 = 0.f;
        #pragma unroll
        for (int c = 0; c < 32; c++) { float d = l[c] - mean2; var2 = fmaf(d, d, var2); }
        var2 *= (1.0f / 32.0f);
        float inv2 = rsqrtf(var2 + 1e-5f);
        #pragma unroll
        for (int c = 0; c < 32; c++)
            y3s[rw * 33 + c] = (l[c] - mean2) * inv2 * sDln3w[c];
    }
    __syncthreads();

    // ---- head: relu(y3 @ Wd0^T) @ Wd1^T ----
    if (tid < 80) {
        int i = tid >> 3, k = tid & 7;
        float acc = 0.f;
        #pragma unroll
        for (int c = 0; c < 32; c++) acc = fmaf(sWd0[k * 33 + c], y3s[i * 33 + c], acc);
        hks[i * 8 + k] = fmaxf(acc, 0.0f);
    }
    __syncthreads();
    if (tid < 10) {
        float z = 0.f;
        #pragma unroll
        for (int k = 0; k < 8; k++) z = fmaf(hks[tid * 8 + k], sWd1[k], z);
        out[((n * 10 + tid) * 30 + pi) * 30 + pj] = z;
    }
}

extern "C" void kernel_launch(void* const* d_in, const int* in_sizes, int n_in,
                              void* d_out, int out_size) {
    const float* x       = (const float*)d_in[0];
    const float* Vf      = (const float*)d_in[1];
    const float* enc_in  = (const float*)d_in[2];
    const float* enc_out = (const float*)d_in[3];
    const float* el1     = (const float*)d_in[4];
    const float* el2     = (const float*)d_in[5];
    const float* eln1    = (const float*)d_in[6];
    const float* eln2    = (const float*)d_in[7];
    const float* ffv     = (const float*)d_in[8];
    const float* sa_in   = (const float*)d_in[9];
    const float* sa_out  = (const float*)d_in[10];
    const float* ca_in   = (const float*)d_in[11];
    const float* ca_out  = (const float*)d_in[12];
    const float* dl1     = (const float*)d_in[13];
    const float* dl2     = (const float*)d_in[14];
    const float* dln1    = (const float*)d_in[15];
    const float* dln2    = (const float*)d_in[16];
    const float* dln3    = (const float*)d_in[17];
    const float* wd0     = (const float*)d_in[18];
    const float* wd1     = (const float*)d_in[19];

    precompute_kernel<<<1, 320>>>(Vf, sa_in, sa_out, dln1, ca_in, ffv);
    main_kernel<<<14400, 128>>>(x, enc_in, enc_out, el1, el2, eln1, eln2, ffv,
                                ca_in, ca_out, dl1, dl2, dln2, dln3, wd0, wd1,
                                (float*)d_out);
}